// round 12
// baseline (speedup 1.0000x reference)
#include <cuda_runtime.h>
#include <math_constants.h>

// Problem shapes (from reference setup_inputs)
#define B_DIM 8
#define C_IN 32
#define C_OUT 32
#define P_DIM 262144
#define K_SH 81                         // (MAX_L+1)^2, MAX_L=8
#define N_ROWS (B_DIM * C_IN)           // 256
#define SPLITS 4
#define CHUNK (P_DIM / SPLITS)          // 65536 elements per block (256 KB)
#define THREADS 256
#define N_RED_BLOCKS (N_ROWS * SPLITS)  // 1024
#define N_M0 9                          // k values with m == 0 (l = 0..8)

// Scratch (no cudaMalloc allowed). g_done is 0 at load; the last block
// resets it to 0 before exiting, so graph replays start clean.
__device__ float g_partials[N_RED_BLOCKS];
__device__ float g_coeffT[N_M0 * C_OUT * C_IN];   // [l][i*C_OUT + o], transposed
__device__ int   g_done;

__global__ void __launch_bounds__(THREADS) fused_kernel(
        const float* __restrict__ in,
        const float* __restrict__ coeff,
        float* __restrict__ out) {

    const int bid = blockIdx.x;

    // ----------------------------------------------------------------------
    // A) Overlapped prologue: blocks 0..80 handle k = bid before streaming.
    //    m != 0  -> write the 256 zeros for this k (one store per thread).
    //    m == 0  -> gather coeff[:,:,k] and store TRANSPOSED into g_coeffT
    //               so the final dot reads coalesced. Hidden under the stream.
    // ----------------------------------------------------------------------
    if (bid < K_SH) {
        const int k = bid;
        int l = 0;
        while ((l + 1) * (l + 1) <= k) ++l;
        const int m = k - l * l - l;

        if (m != 0) {
            const int b = threadIdx.x / C_OUT;
            const int o = threadIdx.x % C_OUT;
            out[((size_t)b * C_OUT + o) * K_SH + k] = 0.0f;
        } else {
            #pragma unroll
            for (int j = 0; j < 4; ++j) {
                const int oi = threadIdx.x + j * THREADS;   // o*C_IN + i
                const int o  = oi / C_IN;
                const int i  = oi % C_IN;
                g_coeffT[l * (C_OUT * C_IN) + i * C_OUT + o] =
                    coeff[(size_t)oi * K_SH + k];
            }
        }
    }

    // ----------------------------------------------------------------------
    // B) Streaming reduce: contiguous 256 KB chunk of one (b, c_in) row.
    // ----------------------------------------------------------------------
    {
        const int row   = bid / SPLITS;
        const int split = bid % SPLITS;
        const float4* __restrict__ p =
            reinterpret_cast<const float4*>(in + (size_t)row * P_DIM + (size_t)split * CHUNK);

        float a0 = 0.f, a1 = 0.f, a2 = 0.f, a3 = 0.f;
        #pragma unroll 4
        for (int jo = 0; jo < 16; ++jo) {
            float4 v0 = __ldcs(&p[threadIdx.x + (jo * 4 + 0) * THREADS]);
            float4 v1 = __ldcs(&p[threadIdx.x + (jo * 4 + 1) * THREADS]);
            float4 v2 = __ldcs(&p[threadIdx.x + (jo * 4 + 2) * THREADS]);
            float4 v3 = __ldcs(&p[threadIdx.x + (jo * 4 + 3) * THREADS]);
            a0 += (v0.x + v0.y) + (v0.z + v0.w);
            a1 += (v1.x + v1.y) + (v1.z + v1.w);
            a2 += (v2.x + v2.y) + (v2.z + v2.w);
            a3 += (v3.x + v3.y) + (v3.z + v3.w);
        }
        float acc = (a0 + a1) + (a2 + a3);

        #pragma unroll
        for (int off = 16; off > 0; off >>= 1)
            acc += __shfl_xor_sync(0xFFFFFFFFu, acc, off);

        __shared__ float warp_sums[THREADS / 32];
        const int lane = threadIdx.x & 31;
        const int wid  = threadIdx.x >> 5;
        if (lane == 0) warp_sums[wid] = acc;
        __syncthreads();

        if (wid == 0) {
            float s = (lane < THREADS / 32) ? warp_sums[lane] : 0.0f;
            #pragma unroll
            for (int off = 4; off > 0; off >>= 1)
                s += __shfl_xor_sync(0xFFFFFFFFu, s, off);
            if (lane == 0) g_partials[bid] = s;
        }
    }
    __syncthreads();   // g_partials store done block-wide

    // ----------------------------------------------------------------------
    // C) Last-block epilogue (no waiting: exactly one block sees old==1023).
    // ----------------------------------------------------------------------
    __shared__ int s_is_last;
    if (threadIdx.x == 0) {
        __threadfence();                          // release partials (+ prologue)
        s_is_last = (atomicAdd(&g_done, 1) == N_RED_BLOCKS - 1);
    }
    __syncthreads();
    if (!s_is_last) return;
    __threadfence();                              // acquire all blocks' writes

    // Fold partials: thread t -> row t (L2-hit loads).
    __shared__ float s_rows[N_ROWS];
    {
        float4 pp = reinterpret_cast<const float4*>(g_partials)[threadIdx.x];
        s_rows[threadIdx.x] = (pp.x + pp.y) + (pp.z + pp.w);
    }
    __syncthreads();

    // 9 outputs per thread: out[b,o,k_l] = Y[l] * sum_i coeffT[l][i,o]*s[b,i]
    const int b = threadIdx.x / C_OUT;
    const int o = threadIdx.x % C_OUT;
    #pragma unroll
    for (int l = 0; l < N_M0; ++l) {
        const int k = l * l + l;
        const float y = sqrtf((2.0f * l + 1.0f) / (4.0f * CUDART_PI_F));
        float acc = 0.0f;
        #pragma unroll
        for (int i = 0; i < C_IN; ++i)
            acc += g_coeffT[l * (C_OUT * C_IN) + i * C_OUT + o] * s_rows[b * C_IN + i];
        out[((size_t)b * C_OUT + o) * K_SH + k] = y * acc;
    }

    // Reset for graph replay (single writer; all observers already returned).
    __syncthreads();
    if (threadIdx.x == 0) g_done = 0;
}

// ---------------------------------------------------------------------------
extern "C" void kernel_launch(void* const* d_in, const int* in_sizes, int n_in,
                              void* d_out, int out_size) {
    const float* input = (const float*)d_in[0];   // [B, C_in, P]
    const float* coeff = (const float*)d_in[1];   // [C_out, C_in, K]
    float* out = (float*)d_out;                   // [B, C_out, K]

    fused_kernel<<<N_RED_BLOCKS, THREADS>>>(input, coeff, out);
}